// round 3
// baseline (speedup 1.0000x reference)
#include <cuda_runtime.h>
#include <math.h>
#include <stdint.h>

#define BB 128
#define RR 4608
#define NR 8                      // r per CTA
#define NCTA (RR/NR)              // 576
#define XPAD 132                  // padded floats per b in x tile (bank-floor LDS)
#define SW_FLOATS (NR*1024)       // 8192  (W tile: [rr][k][i][o])
#define SX_FLOATS (BB*XPAD)       // 16896 (x tile: [b][rr*16+i], padded)
#define SMEM_BYTES ((SW_FLOATS + SX_FLOATS)*4)   // 100352 B
#define INV_B (1.0f/128.0f)
#define INV_R (1.0f/4608.0f)

typedef unsigned long long ull;

// Global scratch
__device__ float g_s0[BB * 64];
__device__ float g_S[2][BB * 64];
__device__ float g_Z[2][2];
__device__ float g_v[2][BB * 64];
__device__ float g_b1[RR * 2];

// ---------------- f32x2 helpers (FFMA2, exact fp32) ------------------------
__device__ __forceinline__ ull pack2(float lo, float hi) {
    ull r; asm("mov.b64 %0, {%1, %2};" : "=l"(r) : "f"(lo), "f"(hi)); return r;
}
__device__ __forceinline__ void unpack2(ull v, float& lo, float& hi) {
    asm("mov.b64 {%0, %1}, %2;" : "=f"(lo), "=f"(hi) : "l"(v));
}
__device__ __forceinline__ ull fma2(ull a, ull b, ull c) {
    ull d; asm("fma.rn.f32x2 %0, %1, %2, %3;" : "=l"(d) : "l"(a), "l"(b), "l"(c));
    return d;
}

// ---------------------------------------------------------------------------
__global__ void zero_kernel() {
    int t = blockIdx.x * blockDim.x + threadIdx.x;   // 8192 threads
    g_s0[t]   = 0.f;
    g_S[0][t] = 0.f;
    g_S[1][t] = 0.f;
    if (t < 4) ((float*)g_Z)[t] = 0.f;
}

// ---------------------------------------------------------------------------
// Cooperative tile load: W[r0..r0+NR) transposed to smem [rr][k][i][o],
// x[b][r0..r0+NR) to smem [b][rr*16+i] (stride XPAD). Front-batched LDGs.
// ---------------------------------------------------------------------------
__device__ __forceinline__ void load_tiles(float* sw, float* sx,
                                           const float* __restrict__ W,
                                           const float* __restrict__ x,
                                           int r0, int t) {
    const float4* Wg = (const float4*)(W + (size_t)r0 * 1024);
    float4 wbuf[4];
    #pragma unroll
    for (int j = 0; j < 4; j++) wbuf[j] = Wg[j * 512 + t];
    float4 xbuf[8];
    #pragma unroll
    for (int j = 0; j < 8; j++) {
        int idx = j * 512 + t;          // float4 id within tile
        int b = idx >> 5, w = idx & 31;
        xbuf[j] = *(const float4*)(x + ((size_t)b * RR + r0) * 16 + w * 4);
    }
    #pragma unroll
    for (int j = 0; j < 4; j++) {
        int f4 = j * 2048 + t * 4;      // global-linear float index of .x
        int rr = f4 >> 10, kk = (f4 >> 9) & 1, o = (f4 >> 4) & 31, i0 = f4 & 15;
        float* s = sw + ((rr * 2 + kk) * 16 + i0) * 32 + o;
        s[0] = wbuf[j].x; s[32] = wbuf[j].y; s[64] = wbuf[j].z; s[96] = wbuf[j].w;
    }
    #pragma unroll
    for (int j = 0; j < 8; j++) {
        int idx = j * 512 + t;
        int b = idx >> 5, w = idx & 31;
        *(float4*)(sx + b * XPAD + w * 4) = xbuf[j];
    }
}

// u[o-pair q] for this thread's (k,oh): 16 i x 8 fma2 from smem W + reg x
__device__ __forceinline__ void compute_u(const float* __restrict__ wb,
                                          const float* __restrict__ xr, ull* u2) {
    #pragma unroll
    for (int q = 0; q < 8; q++) u2[q] = 0ull;
    #pragma unroll
    for (int i = 0; i < 16; i++) {
        ull xi2 = pack2(xr[i], xr[i]);
        const float* wrow = wb + i * 32;
        #pragma unroll
        for (int q = 0; q < 4; q++) {
            ulonglong2 w = *(const ulonglong2*)(wrow + q * 4);
            u2[2 * q]     = fma2(w.x, xi2, u2[2 * q]);
            u2[2 * q + 1] = fma2(w.y, xi2, u2[2 * q + 1]);
        }
    }
}

// ---------------------------------------------------------------------------
// Pass 0: s0[b,k,o] = sum_{r,i} x[b,r,i] W[r,k,o,i]  (uniform c = 1/R later)
// 512 threads = 128 b x 2 k x 2 o-halves; no in-loop barriers.
// ---------------------------------------------------------------------------
__global__ __launch_bounds__(512, 1) void pass0_kernel(const float* __restrict__ x,
                                                       const float* __restrict__ W) {
    extern __shared__ float dsm[];
    float* sw = dsm;
    float* sx = dsm + SW_FLOATS;
    const int t  = threadIdx.x;
    const int b  = t & 127;
    const int oh = (t >> 7) & 1;
    const int k  = t >> 8;
    const int r0 = blockIdx.x * NR;

    load_tiles(sw, sx, W, x, r0, t);
    __syncthreads();

    const float* wbase = sw + k * 512 + oh * 16;
    ull S2[8];
    #pragma unroll
    for (int q = 0; q < 8; q++) S2[q] = 0ull;

    #pragma unroll 1
    for (int rr = 0; rr < NR; ++rr) {
        float xr[16];
        #pragma unroll
        for (int j = 0; j < 4; j++)
            *(float4*)(xr + 4 * j) = *(const float4*)(sx + b * XPAD + rr * 16 + 4 * j);
        const float* wb = wbase + rr * 1024;
        #pragma unroll
        for (int i = 0; i < 16; i++) {
            ull xi2 = pack2(xr[i], xr[i]);
            const float* wrow = wb + i * 32;
            #pragma unroll
            for (int q = 0; q < 4; q++) {
                ulonglong2 w = *(const ulonglong2*)(wrow + q * 4);
                S2[2 * q]     = fma2(w.x, xi2, S2[2 * q]);
                S2[2 * q + 1] = fma2(w.y, xi2, S2[2 * q + 1]);
            }
        }
    }

    float* sp = g_s0 + b * 64 + k * 32 + oh * 16;
    #pragma unroll
    for (int q = 0; q < 8; q++) {
        float lo, hi; unpack2(S2[q], lo, hi);
        atomicAdd(sp + 2 * q, lo);
        atomicAdd(sp + 2 * q + 1, hi);
    }
}

// ---------------------------------------------------------------------------
// Routing pass (deferred softmax), two phases, 2 barriers total:
//  A: dot[rr,warp] partials (free-running warps)
//  e: 16 threads compute e[rr,k] = exp(bprev + mean_b<u,v>)
//  B: S[b,k,o] += e * u  (u recomputed from smem tiles)
// ---------------------------------------------------------------------------
__global__ __launch_bounds__(512, 1) void routing_kernel(const float* __restrict__ x,
                                                         const float* __restrict__ W,
                                                         int pass) {
    extern __shared__ float dsm[];
    float* sw = dsm;
    float* sx = dsm + SW_FLOATS;
    __shared__ float red[NR][16];
    __shared__ float ebc[NR * 2];
    const int t    = threadIdx.x;
    const int b    = t & 127;
    const int oh   = (t >> 7) & 1;
    const int k    = t >> 8;
    const int warp = t >> 5;
    const int lane = t & 31;
    const int r0   = blockIdx.x * NR;

    load_tiles(sw, sx, W, x, r0, t);

    ull v2[8];
    {
        const float4* vp = (const float4*)(g_v[pass] + b * 64 + k * 32 + oh * 16);
        #pragma unroll
        for (int j = 0; j < 4; j++) {
            float4 q = vp[j];
            v2[2 * j]     = pack2(q.x, q.y);
            v2[2 * j + 1] = pack2(q.z, q.w);
        }
    }
    __syncthreads();

    const float* wbase = sw + k * 512 + oh * 16;

    // ---- phase A: agreement dots ----
    #pragma unroll 1
    for (int rr = 0; rr < NR; ++rr) {
        float xr[16];
        #pragma unroll
        for (int j = 0; j < 4; j++)
            *(float4*)(xr + 4 * j) = *(const float4*)(sx + b * XPAD + rr * 16 + 4 * j);
        ull u2[8];
        compute_u(wbase + rr * 1024, xr, u2);
        ull d2 = 0ull;
        #pragma unroll
        for (int q = 0; q < 8; q++) d2 = fma2(u2[q], v2[q], d2);
        float dl, dh; unpack2(d2, dl, dh);
        float dot = dl + dh;
        #pragma unroll
        for (int m = 16; m >= 1; m >>= 1) dot += __shfl_xor_sync(0xffffffffu, dot, m);
        if (lane == 0) red[rr][warp] = dot;
    }
    __syncthreads();

    // ---- e stage: 16 threads, one per (rr,k) ----
    if (t < 2 * NR) {
        const int rr = t >> 1, kk = t & 1;
        float a = 0.f;
        #pragma unroll
        for (int w = 0; w < 8; w++) a += red[rr][kk * 8 + w];
        a *= INV_B;
        float bn = a;
        const int gi = (r0 + rr) * 2 + kk;
        if (pass) bn += g_b1[gi];
        else      g_b1[gi] = bn;
        ebc[t] = expf(bn);
    }
    __syncthreads();

    if (t < 2) {
        float zs = 0.f;
        #pragma unroll
        for (int rr = 0; rr < NR; rr++) zs += ebc[2 * rr + t];
        atomicAdd(&g_Z[pass][t], zs);
    }

    // ---- phase B: weighted sums ----
    ull S2[8];
    #pragma unroll
    for (int q = 0; q < 8; q++) S2[q] = 0ull;

    #pragma unroll 1
    for (int rr = 0; rr < NR; ++rr) {
        float xr[16];
        #pragma unroll
        for (int j = 0; j < 4; j++)
            *(float4*)(xr + 4 * j) = *(const float4*)(sx + b * XPAD + rr * 16 + 4 * j);
        ull u2[8];
        compute_u(wbase + rr * 1024, xr, u2);
        const float e = ebc[rr * 2 + k];
        ull e2 = pack2(e, e);
        #pragma unroll
        for (int q = 0; q < 8; q++) S2[q] = fma2(u2[q], e2, S2[q]);
    }

    float* sp = g_S[pass] + b * 64 + k * 32 + oh * 16;
    #pragma unroll
    for (int q = 0; q < 8; q++) {
        float lo, hi; unpack2(S2[q], lo, hi);
        atomicAdd(sp + 2 * q, lo);
        atomicAdd(sp + 2 * q + 1, hi);
    }
}

// ---------------------------------------------------------------------------
// Squash: one warp per (b,k); lane = o.
// mode 0: v0 = squash(s0/R); mode 1: v1 = squash(S0/Z0); mode 2: out = squash(S1/Z1)
// ---------------------------------------------------------------------------
__global__ void squash_kernel(int mode, float* __restrict__ out) {
    const int t = blockIdx.x * blockDim.x + threadIdx.x;  // 8192
    const int k = (t >> 5) & 1;
    float s;
    if (mode == 0) {
        s = g_s0[t] * INV_R;
    } else {
        const int p = mode - 1;
        s = g_S[p][t] / g_Z[p][k];
    }
    float sq = s * s;
    #pragma unroll
    for (int m = 16; m >= 1; m >>= 1) sq += __shfl_xor_sync(0xffffffffu, sq, m);
    const float sn = sq;
    const float f = sqrtf(sn) / (0.5f + sn);
    const float v = s * f;
    if (mode == 2) out[t] = v;
    else           g_v[mode][t] = v;
}

// ---------------------------------------------------------------------------
extern "C" void kernel_launch(void* const* d_in, const int* in_sizes, int n_in,
                              void* d_out, int out_size) {
    const float* x = (const float*)d_in[0];   // [128, 4608, 16]
    const float* W = (const float*)d_in[1];   // [1, 4608, 2, 32, 16]
    float* out = (float*)d_out;               // [128, 2, 32]

    cudaFuncSetAttribute(pass0_kernel,
                         cudaFuncAttributeMaxDynamicSharedMemorySize, SMEM_BYTES);
    cudaFuncSetAttribute(routing_kernel,
                         cudaFuncAttributeMaxDynamicSharedMemorySize, SMEM_BYTES);

    zero_kernel<<<32, 256>>>();
    pass0_kernel<<<NCTA, 512, SMEM_BYTES>>>(x, W);
    squash_kernel<<<32, 256>>>(0, nullptr);           // v0
    routing_kernel<<<NCTA, 512, SMEM_BYTES>>>(x, W, 0);
    squash_kernel<<<32, 256>>>(1, nullptr);           // v1
    routing_kernel<<<NCTA, 512, SMEM_BYTES>>>(x, W, 1);
    squash_kernel<<<32, 256>>>(2, out);               // final v -> out
}

// round 5
// speedup vs baseline: 3.7316x; 3.7316x over previous
#include <cuda_runtime.h>
#include <cuda_fp16.h>
#include <math.h>
#include <stdint.h>

#define BB 128
#define RR 4608
#define NR 8                 // r per batch
#define NBATCH 4
#define NRB (NR*NBATCH)      // 32 r per CTA
#define NCTA (RR/NRB)        // 144 -> one wave
#define INV_B (1.0f/128.0f)
#define INV_R (1.0f/4608.0f)

// smem tile geometry (48-byte padded rows -> conflict-free fragment LDS)
#define XROW 48
#define XT_RL (128*XROW)     // 6144 B per rl
#define WT_RL (64*XROW)      // 3072 B per rl
#define DSM_BYTES (NR*XT_RL + NR*WT_RL)   // 49152+24576 = 73728

typedef unsigned long long ull;

// fp16 copies of inputs (converted once per launch)
__device__ __half g_xh[(size_t)RR * BB * 16];    // [r][b][i]
__device__ __half g_wh[(size_t)RR * 64 * 16];    // [r][ko][i]
__device__ float g_part[NCTA][BB * 64];
__device__ float g_Zf[4];
__device__ float g_v[2][BB * 64];
__device__ float g_b1[RR * 2];

// ---------------- f32x2 helpers ------------------------------------------
__device__ __forceinline__ ull pack2(float lo, float hi) {
    ull r; asm("mov.b64 %0, {%1, %2};" : "=l"(r) : "f"(lo), "f"(hi)); return r;
}
__device__ __forceinline__ void unpack2(ull v, float& lo, float& hi) {
    asm("mov.b64 {%0, %1}, %2;" : "=f"(lo), "=f"(hi) : "l"(v));
}
__device__ __forceinline__ ull fma2(ull a, ull b, ull c) {
    ull d; asm("fma.rn.f32x2 %0, %1, %2, %3;" : "=l"(d) : "l"(a), "l"(b), "l"(c));
    return d;
}

// ---------------- m16n8k16 f16 MMA ---------------------------------------
__device__ __forceinline__ void mma16816(float* d, const uint32_t* a,
                                         const uint32_t* b, const float* c) {
    asm volatile(
        "mma.sync.aligned.m16n8k16.row.col.f32.f16.f16.f32 "
        "{%0,%1,%2,%3}, {%4,%5,%6,%7}, {%8,%9}, {%10,%11,%12,%13};"
        : "=f"(d[0]), "=f"(d[1]), "=f"(d[2]), "=f"(d[3])
        : "r"(a[0]), "r"(a[1]), "r"(a[2]), "r"(a[3]),
          "r"(b[0]), "r"(b[1]),
          "f"(c[0]), "f"(c[1]), "f"(c[2]), "f"(c[3]));
}

// ---------------------------------------------------------------------------
__global__ void zeroZ_kernel() { if (threadIdx.x < 4) g_Zf[threadIdx.x] = 0.f; }

// W[r][k][o][i] fp32 -> fp16, same order. 4.72M elems / 4 per thread.
__global__ void conv_w_kernel(const float4* __restrict__ w4) {
    size_t i = (size_t)blockIdx.x * blockDim.x + threadIdx.x;  // 1179648
    float4 v = w4[i];
    __half2 lo = __float22half2_rn(make_float2(v.x, v.y));
    __half2 hi = __float22half2_rn(make_float2(v.z, v.w));
    uint2 o; o.x = *(uint32_t*)&lo; o.y = *(uint32_t*)&hi;
    ((uint2*)g_wh)[i] = o;
}

// x[b][r][i] fp32 -> g_xh[r][b][i] fp16, tiled 32b x 32r transpose via smem.
__global__ __launch_bounds__(256) void conv_x_kernel(const float4* __restrict__ x4) {
    __shared__ uint2 sx[32][132];     // [rr][b*4+q], padded
    const int t = threadIdx.x;
    const int r0 = blockIdx.x * 32, b0 = blockIdx.y * 32;
    #pragma unroll
    for (int j = 0; j < 16; j++) {
        int idx = j * 256 + t;        // over [b][rr][q]
        int b = idx >> 7, rem = idx & 127, rr = rem >> 2, q = rem & 3;
        float4 v = x4[((size_t)(b0 + b) * RR + r0 + rr) * 4 + q];
        __half2 lo = __float22half2_rn(make_float2(v.x, v.y));
        __half2 hi = __float22half2_rn(make_float2(v.z, v.w));
        uint2 o; o.x = *(uint32_t*)&lo; o.y = *(uint32_t*)&hi;
        sx[rr][b * 4 + q] = o;
    }
    __syncthreads();
    #pragma unroll
    for (int j = 0; j < 16; j++) {
        int idx = j * 256 + t;        // over [rr][b][q]
        int rr = idx >> 7, rem = idx & 127, b = rem >> 2, q = rem & 3;
        ((uint2*)g_xh)[((size_t)(r0 + rr) * BB + b0 + b) * 4 + q] = sx[rr][b * 4 + q];
    }
}

// ---------------------------------------------------------------------------
// Stage one 8-r batch: xt[rl][b][i] (48B rows), wt[rl][ko][i] (48B rows).
// ---------------------------------------------------------------------------
__device__ __forceinline__ void stage_tiles(char* xt, char* wt, int r0, int t) {
    #pragma unroll
    for (int j = 0; j < 8; j++) {
        int idx = j * 512 + t;                      // 4096 uint2
        int rl = idx >> 9, rem = idx & 511, b = rem >> 2, q = rem & 3;
        uint2 v = ((const uint2*)g_xh)[((size_t)(r0 + rl) * BB + b) * 4 + q];
        *(uint2*)(xt + rl * XT_RL + b * XROW + q * 8) = v;
    }
    #pragma unroll
    for (int j = 0; j < 4; j++) {
        int idx = j * 512 + t;                      // 2048 uint2
        int rl = idx >> 8, rem = idx & 255, ko = rem >> 2, q = rem & 3;
        uint2 v = ((const uint2*)g_wh)[((size_t)(r0 + rl) * 64 + ko) * 4 + q];
        *(uint2*)(wt + rl * WT_RL + ko * XROW + q * 8) = v;
    }
}

// A fragment (x) for warp m-tile, this rl.
__device__ __forceinline__ void load_a(const char* xb, uint32_t* A) {
    A[0] = *(const uint32_t*)(xb);
    A[1] = *(const uint32_t*)(xb + 8 * XROW);
    A[2] = *(const uint32_t*)(xb + 16);
    A[3] = *(const uint32_t*)(xb + 8 * XROW + 16);
}

// ---------------------------------------------------------------------------
// Pass 0: s0 partial = sum over this CTA's 32 r of u_hat, via C-frag accum.
// 16 warps = 8 m-tiles x 2 k-halves; each warp 4 n-tiles of 8.
// ---------------------------------------------------------------------------
__global__ __launch_bounds__(512, 1) void pass0_mma() {
    extern __shared__ char dsm[];
    char* xt = dsm;
    char* wt = dsm + NR * XT_RL;
    const int t = threadIdx.x, lane = t & 31, w = t >> 5;
    const int m = w & 7, kh = w >> 3;
    const int gp = lane >> 2, tig = lane & 3;
    const int xoff = (m * 16 + gp) * XROW + tig * 4;
    const int woff = (kh * 32 + gp) * XROW + tig * 4;

    float CF[4][4];
    #pragma unroll
    for (int nt = 0; nt < 4; nt++)
        #pragma unroll
        for (int c = 0; c < 4; c++) CF[nt][c] = 0.f;

    const int rc = blockIdx.x * NRB;
    for (int bt = 0; bt < NBATCH; bt++) {
        __syncthreads();
        stage_tiles(xt, wt, rc + bt * NR, t);
        __syncthreads();
        #pragma unroll
        for (int rl = 0; rl < NR; rl++) {
            uint32_t A[4];
            load_a(xt + rl * XT_RL + xoff, A);
            const char* wb = wt + rl * WT_RL + woff;
            #pragma unroll
            for (int nt = 0; nt < 4; nt++) {
                uint32_t Bf[2];
                Bf[0] = *(const uint32_t*)(wb + nt * 8 * XROW);
                Bf[1] = *(const uint32_t*)(wb + nt * 8 * XROW + 16);
                mma16816(CF[nt], A, Bf, CF[nt]);
            }
        }
    }
    float* dst = g_part[blockIdx.x];
    #pragma unroll
    for (int nt = 0; nt < 4; nt++) {
        const int ko = kh * 32 + nt * 8 + 2 * tig;
        const int b0 = m * 16 + gp;
        *(float2*)&dst[b0 * 64 + ko]       = make_float2(CF[nt][0], CF[nt][1]);
        *(float2*)&dst[(b0 + 8) * 64 + ko] = make_float2(CF[nt][2], CF[nt][3]);
    }
}

// ---------------------------------------------------------------------------
// Routing pass (deferred softmax): per 8-r batch:
//  sweep1: u via mma, dot partials -> red | e-stage | sweep2: u again, S += e*u
// ---------------------------------------------------------------------------
__global__ __launch_bounds__(512, 1) void routing_mma(int pass) {
    extern __shared__ char dsm[];
    char* xt = dsm;
    char* wt = dsm + NR * XT_RL;
    __shared__ float red[NR * 2 * 128];
    __shared__ float ebc[16];
    const int t = threadIdx.x, lane = t & 31, w = t >> 5;
    const int m = w & 7, kh = w >> 3;
    const int gp = lane >> 2, tig = lane & 3;
    const int xoff = (m * 16 + gp) * XROW + tig * 4;
    const int woff = (kh * 32 + gp) * XROW + tig * 4;

    // v fragments: v2[row][nt] covers (b=m*16+gp+row*8, ko=kh*32+nt*8+2*tig{,+1})
    ull v2[2][4];
    {
        const float* vp = g_v[pass];
        #pragma unroll
        for (int row = 0; row < 2; row++) {
            const int b = m * 16 + gp + row * 8;
            #pragma unroll
            for (int nt = 0; nt < 4; nt++) {
                float2 q = *(const float2*)&vp[b * 64 + kh * 32 + nt * 8 + 2 * tig];
                v2[row][nt] = pack2(q.x, q.y);
            }
        }
    }
    ull S2[2][4];
    #pragma unroll
    for (int row = 0; row < 2; row++)
        #pragma unroll
        for (int nt = 0; nt < 4; nt++) S2[row][nt] = 0ull;
    float zacc = 0.f;

    const int rc = blockIdx.x * NRB;
    for (int bt = 0; bt < NBATCH; bt++) {
        const int r0 = rc + bt * NR;
        __syncthreads();
        stage_tiles(xt, wt, r0, t);
        __syncthreads();

        // ---- sweep 1: agreement dots ----
        #pragma unroll 2
        for (int rl = 0; rl < NR; rl++) {
            uint32_t A[4];
            load_a(xt + rl * XT_RL + xoff, A);
            const char* wb = wt + rl * WT_RL + woff;
            ull d0 = 0ull, d1 = 0ull;
            #pragma unroll
            for (int nt = 0; nt < 4; nt++) {
                uint32_t Bf[2];
                Bf[0] = *(const uint32_t*)(wb + nt * 8 * XROW);
                Bf[1] = *(const uint32_t*)(wb + nt * 8 * XROW + 16);
                float C[4] = {0.f, 0.f, 0.f, 0.f};
                mma16816(C, A, Bf, C);
                d0 = fma2(pack2(C[0], C[1]), v2[0][nt], d0);
                d1 = fma2(pack2(C[2], C[3]), v2[1][nt], d1);
            }
            float l0, h0, l1, h1;
            unpack2(d0, l0, h0); unpack2(d1, l1, h1);
            float dr0 = l0 + h0, dr1 = l1 + h1;
            dr0 += __shfl_xor_sync(0xffffffffu, dr0, 1);
            dr0 += __shfl_xor_sync(0xffffffffu, dr0, 2);
            dr1 += __shfl_xor_sync(0xffffffffu, dr1, 1);
            dr1 += __shfl_xor_sync(0xffffffffu, dr1, 2);
            if (tig == 0) {
                float* rrow = &red[(rl * 2 + kh) * 128];
                rrow[m * 16 + gp]     = dr0;
                rrow[m * 16 + gp + 8] = dr1;
            }
        }
        __syncthreads();

        // ---- e stage: warp w handles (rl = w>>1, k = w&1) ----
        {
            const int rl = w >> 1, kk = w & 1;
            const float* rrow = &red[(rl * 2 + kk) * 128];
            float s = rrow[lane] + rrow[lane + 32] + rrow[lane + 64] + rrow[lane + 96];
            #pragma unroll
            for (int sh = 16; sh >= 1; sh >>= 1)
                s += __shfl_xor_sync(0xffffffffu, s, sh);
            if (lane == 0) {
                float a = s * INV_B;
                const int gi = (r0 + rl) * 2 + kk;
                float bn = a;
                if (pass) bn += g_b1[gi];
                else      g_b1[gi] = bn;
                float e = expf(bn);
                ebc[rl * 2 + kk] = e;
                zacc += e;
            }
        }
        __syncthreads();

        // ---- sweep 2: weighted sums ----
        #pragma unroll 2
        for (int rl = 0; rl < NR; rl++) {
            uint32_t A[4];
            load_a(xt + rl * XT_RL + xoff, A);
            const char* wb = wt + rl * WT_RL + woff;
            const float e = ebc[rl * 2 + kh];
            const ull e2 = pack2(e, e);
            #pragma unroll
            for (int nt = 0; nt < 4; nt++) {
                uint32_t Bf[2];
                Bf[0] = *(const uint32_t*)(wb + nt * 8 * XROW);
                Bf[1] = *(const uint32_t*)(wb + nt * 8 * XROW + 16);
                float C[4] = {0.f, 0.f, 0.f, 0.f};
                mma16816(C, A, Bf, C);
                S2[0][nt] = fma2(pack2(C[0], C[1]), e2, S2[0][nt]);
                S2[1][nt] = fma2(pack2(C[2], C[3]), e2, S2[1][nt]);
            }
        }
    }

    float* dst = g_part[blockIdx.x];
    #pragma unroll
    for (int nt = 0; nt < 4; nt++) {
        const int ko = kh * 32 + nt * 8 + 2 * tig;
        const int b0 = m * 16 + gp;
        float lo, hi;
        unpack2(S2[0][nt], lo, hi);
        *(float2*)&dst[b0 * 64 + ko] = make_float2(lo, hi);
        unpack2(S2[1][nt], lo, hi);
        *(float2*)&dst[(b0 + 8) * 64 + ko] = make_float2(lo, hi);
    }
    if (lane == 0) atomicAdd(&g_Zf[pass * 2 + (w & 1)], zacc);
}

// ---------------------------------------------------------------------------
// Squash: sum 144 partials, normalize, squash. Warp per (b,k), lane = o.
// ---------------------------------------------------------------------------
__global__ void squash_kernel(int mode, float* __restrict__ out) {
    const int t = blockIdx.x * blockDim.x + threadIdx.x;   // 8192
    const int k = (t >> 5) & 1;
    float s = 0.f;
    #pragma unroll 4
    for (int c = 0; c < NCTA; c++) s += g_part[c][t];
    if (mode == 0) s *= INV_R;
    else           s /= g_Zf[(mode - 1) * 2 + k];
    float sq = s * s;
    #pragma unroll
    for (int m = 16; m >= 1; m >>= 1) sq += __shfl_xor_sync(0xffffffffu, sq, m);
    const float sn = sq;
    const float f = sqrtf(sn) / (0.5f + sn);
    const float v = s * f;
    if (mode == 2) out[t] = v;
    else           g_v[mode][t] = v;
}

// ---------------------------------------------------------------------------
extern "C" void kernel_launch(void* const* d_in, const int* in_sizes, int n_in,
                              void* d_out, int out_size) {
    const float* x = (const float*)d_in[0];   // [128, 4608, 16]
    const float* W = (const float*)d_in[1];   // [1, 4608, 2, 32, 16]
    float* out = (float*)d_out;               // [128, 2, 32]

    cudaFuncSetAttribute(pass0_mma,
                         cudaFuncAttributeMaxDynamicSharedMemorySize, DSM_BYTES);
    cudaFuncSetAttribute(routing_mma,
                         cudaFuncAttributeMaxDynamicSharedMemorySize, DSM_BYTES);

    zeroZ_kernel<<<1, 32>>>();
    conv_w_kernel<<<1152, 1024>>>((const float4*)W);
    conv_x_kernel<<<dim3(RR / 32, BB / 32), 256>>>((const float4*)x);
    pass0_mma<<<NCTA, 512, DSM_BYTES>>>();
    squash_kernel<<<32, 256>>>(0, nullptr);
    routing_mma<<<NCTA, 512, DSM_BYTES>>>(0);
    squash_kernel<<<32, 256>>>(1, nullptr);
    routing_mma<<<NCTA, 512, DSM_BYTES>>>(1);
    squash_kernel<<<32, 256>>>(2, out);
}

// round 6
// speedup vs baseline: 4.2770x; 1.1462x over previous
#include <cuda_runtime.h>
#include <cuda_fp16.h>
#include <math.h>
#include <stdint.h>

#define BB 128
#define RR 4608
#define NR 8                 // r per staged batch
#define NBATCH 4
#define NRB (NR*NBATCH)      // 32 r per CTA
#define NCTA (RR/NRB)        // 144 -> one wave
#define INV_B (1.0f/128.0f)
#define INV_R (1.0f/4608.0f)

// smem tile geometry (48-byte padded rows -> conflict-free fragment LDS)
#define XROW 48
#define XT_RL (128*XROW)     // 6144 B per rl
#define WT_RL (64*XROW)      // 3072 B per rl
#define DSM_BYTES (NR*XT_RL + NR*WT_RL)   // 73728

typedef unsigned long long ull;

// fp16 copies of inputs (written by pass0 while it computes)
__device__ __half g_xh[(size_t)RR * BB * 16];    // [r][b][i]
__device__ __half g_wh[(size_t)RR * 64 * 16];    // [r][ko][i]
__device__ float g_part[NCTA][BB * 64];
__device__ float g_Zf[4];
__device__ float g_v[2][BB * 64];
__device__ float g_b1[RR * 2];

// ---------------- f32x2 helpers ------------------------------------------
__device__ __forceinline__ ull pack2(float lo, float hi) {
    ull r; asm("mov.b64 %0, {%1, %2};" : "=l"(r) : "f"(lo), "f"(hi)); return r;
}
__device__ __forceinline__ void unpack2(ull v, float& lo, float& hi) {
    asm("mov.b64 {%0, %1}, %2;" : "=f"(lo), "=f"(hi) : "l"(v));
}
__device__ __forceinline__ ull fma2(ull a, ull b, ull c) {
    ull d; asm("fma.rn.f32x2 %0, %1, %2, %3;" : "=l"(d) : "l"(a), "l"(b), "l"(c));
    return d;
}

// ---------------- m16n8k16 f16 MMA ---------------------------------------
__device__ __forceinline__ void mma16816(float* d, const uint32_t* a,
                                         const uint32_t* b, const float* c) {
    asm volatile(
        "mma.sync.aligned.m16n8k16.row.col.f32.f16.f16.f32 "
        "{%0,%1,%2,%3}, {%4,%5,%6,%7}, {%8,%9}, {%10,%11,%12,%13};"
        : "=f"(d[0]), "=f"(d[1]), "=f"(d[2]), "=f"(d[3])
        : "r"(a[0]), "r"(a[1]), "r"(a[2]), "r"(a[3]),
          "r"(b[0]), "r"(b[1]),
          "f"(c[0]), "f"(c[1]), "f"(c[2]), "f"(c[3]));
}

__device__ __forceinline__ uint2 cvt4(float4 v) {
    __half2 lo = __float22half2_rn(make_float2(v.x, v.y));
    __half2 hi = __float22half2_rn(make_float2(v.z, v.w));
    uint2 o; o.x = *(uint32_t*)&lo; o.y = *(uint32_t*)&hi;
    return o;
}

// ---------------------------------------------------------------------------
// Staging. pass0 variant: read fp32 inputs, convert, store tile + fp16 globals.
// routing variant: read the fp16 globals.
// ---------------------------------------------------------------------------
__device__ __forceinline__ void stage_conv(char* xt, char* wt,
                                           const float4* __restrict__ x4,
                                           const float4* __restrict__ w4,
                                           int r0, int t) {
    #pragma unroll
    for (int j = 0; j < 8; j++) {
        int idx = j * 512 + t;                      // 4096 uint2
        int rl = idx >> 9, rem = idx & 511, b = rem >> 2, q = rem & 3;
        uint2 u = cvt4(x4[((size_t)b * RR + r0 + rl) * 4 + q]);
        *(uint2*)(xt + rl * XT_RL + b * XROW + q * 8) = u;
        ((uint2*)g_xh)[((size_t)(r0 + rl) * BB + b) * 4 + q] = u;
    }
    #pragma unroll
    for (int j = 0; j < 4; j++) {
        int idx = j * 512 + t;                      // 2048 uint2
        int rl = idx >> 8, rem = idx & 255, ko = rem >> 2, q = rem & 3;
        uint2 u = cvt4(w4[((size_t)(r0 + rl) * 64 + ko) * 4 + q]);
        *(uint2*)(wt + rl * WT_RL + ko * XROW + q * 8) = u;
        ((uint2*)g_wh)[((size_t)(r0 + rl) * 64 + ko) * 4 + q] = u;
    }
}

__device__ __forceinline__ void stage_tiles(char* xt, char* wt, int r0, int t) {
    #pragma unroll
    for (int j = 0; j < 8; j++) {
        int idx = j * 512 + t;
        int rl = idx >> 9, rem = idx & 511, b = rem >> 2, q = rem & 3;
        uint2 v = ((const uint2*)g_xh)[((size_t)(r0 + rl) * BB + b) * 4 + q];
        *(uint2*)(xt + rl * XT_RL + b * XROW + q * 8) = v;
    }
    #pragma unroll
    for (int j = 0; j < 4; j++) {
        int idx = j * 512 + t;
        int rl = idx >> 8, rem = idx & 255, ko = rem >> 2, q = rem & 3;
        uint2 v = ((const uint2*)g_wh)[((size_t)(r0 + rl) * 64 + ko) * 4 + q];
        *(uint2*)(wt + rl * WT_RL + ko * XROW + q * 8) = v;
    }
}

__device__ __forceinline__ void load_a(const char* xb, uint32_t* A) {
    A[0] = *(const uint32_t*)(xb);
    A[1] = *(const uint32_t*)(xb + 8 * XROW);
    A[2] = *(const uint32_t*)(xb + 16);
    A[3] = *(const uint32_t*)(xb + 8 * XROW + 16);
}

// ---------------------------------------------------------------------------
// Pass 0 (+input conversion): s0 partial = sum over 32 r of u_hat via C accum.
// ---------------------------------------------------------------------------
__global__ __launch_bounds__(512, 1) void pass0_mma(const float4* __restrict__ x4,
                                                    const float4* __restrict__ w4) {
    extern __shared__ char dsm[];
    char* xt = dsm;
    char* wt = dsm + NR * XT_RL;
    const int t = threadIdx.x, lane = t & 31, w = t >> 5;
    const int m = w & 7, kh = w >> 3;
    const int gp = lane >> 2, tig = lane & 3;
    const int xoff = (m * 16 + gp) * XROW + tig * 4;
    const int woff = (kh * 32 + gp) * XROW + tig * 4;

    float CF[4][4];
    #pragma unroll
    for (int nt = 0; nt < 4; nt++)
        #pragma unroll
        for (int c = 0; c < 4; c++) CF[nt][c] = 0.f;

    const int rc = blockIdx.x * NRB;
    for (int bt = 0; bt < NBATCH; bt++) {
        if (bt) __syncthreads();
        stage_conv(xt, wt, x4, w4, rc + bt * NR, t);
        __syncthreads();
        #pragma unroll
        for (int rl = 0; rl < NR; rl++) {
            uint32_t A[4];
            load_a(xt + rl * XT_RL + xoff, A);
            const char* wb = wt + rl * WT_RL + woff;
            #pragma unroll
            for (int nt = 0; nt < 4; nt++) {
                uint32_t Bf[2];
                Bf[0] = *(const uint32_t*)(wb + nt * 8 * XROW);
                Bf[1] = *(const uint32_t*)(wb + nt * 8 * XROW + 16);
                mma16816(CF[nt], A, Bf, CF[nt]);
            }
        }
    }
    float* dst = g_part[blockIdx.x];
    #pragma unroll
    for (int nt = 0; nt < 4; nt++) {
        const int ko = kh * 32 + nt * 8 + 2 * tig;
        const int b0 = m * 16 + gp;
        *(float2*)&dst[b0 * 64 + ko]       = make_float2(CF[nt][0], CF[nt][1]);
        *(float2*)&dst[(b0 + 8) * 64 + ko] = make_float2(CF[nt][2], CF[nt][3]);
    }
}

// ---------------------------------------------------------------------------
// Routing pass (deferred softmax), single sweep with retained C fragments.
// Mini-batch of 4 rl: MMA+dots -> bar -> e-stage -> bar -> S += e*C (regs).
// ---------------------------------------------------------------------------
__global__ __launch_bounds__(512, 1) void routing_mma(int pass) {
    extern __shared__ char dsm[];
    char* xt = dsm;
    char* wt = dsm + NR * XT_RL;
    __shared__ float red[4][2][128];
    __shared__ float ebc[8];
    const int t = threadIdx.x, lane = t & 31, w = t >> 5;
    const int m = w & 7, kh = w >> 3;
    const int gp = lane >> 2, tig = lane & 3;
    const int xoff = (m * 16 + gp) * XROW + tig * 4;
    const int woff = (kh * 32 + gp) * XROW + tig * 4;

    // v fragments: v2[row][nt] covers (b=m*16+gp+row*8, ko=kh*32+nt*8+2*tig{,+1})
    ull v2[2][4];
    {
        const float* vp = g_v[pass];
        #pragma unroll
        for (int row = 0; row < 2; row++) {
            const int b = m * 16 + gp + row * 8;
            #pragma unroll
            for (int nt = 0; nt < 4; nt++) {
                float2 q = *(const float2*)&vp[b * 64 + kh * 32 + nt * 8 + 2 * tig];
                v2[row][nt] = pack2(q.x, q.y);
            }
        }
    }
    ull S2[2][4];
    #pragma unroll
    for (int row = 0; row < 2; row++)
        #pragma unroll
        for (int nt = 0; nt < 4; nt++) S2[row][nt] = 0ull;
    float zacc = 0.f;

    const int rc = blockIdx.x * NRB;
    for (int bt = 0; bt < NBATCH; bt++) {
        const int r0 = rc + bt * NR;
        stage_tiles(xt, wt, r0, t);
        __syncthreads();

        #pragma unroll
        for (int mini = 0; mini < 2; mini++) {
            float CF[4][4][4];   // [rlm][nt][c] retained across the e barrier

            // ---- sweep: u fragments + agreement dots ----
            #pragma unroll
            for (int rlm = 0; rlm < 4; rlm++) {
                const int rl = mini * 4 + rlm;
                uint32_t A[4];
                load_a(xt + rl * XT_RL + xoff, A);
                const char* wb = wt + rl * WT_RL + woff;
                ull d0 = 0ull, d1 = 0ull;
                #pragma unroll
                for (int nt = 0; nt < 4; nt++) {
                    uint32_t Bf[2];
                    Bf[0] = *(const uint32_t*)(wb + nt * 8 * XROW);
                    Bf[1] = *(const uint32_t*)(wb + nt * 8 * XROW + 16);
                    float* C = CF[rlm][nt];
                    C[0] = 0.f; C[1] = 0.f; C[2] = 0.f; C[3] = 0.f;
                    mma16816(C, A, Bf, C);
                    d0 = fma2(pack2(C[0], C[1]), v2[0][nt], d0);
                    d1 = fma2(pack2(C[2], C[3]), v2[1][nt], d1);
                }
                float l0, h0, l1, h1;
                unpack2(d0, l0, h0); unpack2(d1, l1, h1);
                float dr0 = l0 + h0, dr1 = l1 + h1;
                dr0 += __shfl_xor_sync(0xffffffffu, dr0, 1);
                dr0 += __shfl_xor_sync(0xffffffffu, dr0, 2);
                dr1 += __shfl_xor_sync(0xffffffffu, dr1, 1);
                dr1 += __shfl_xor_sync(0xffffffffu, dr1, 2);
                if (tig == 0) {
                    red[rlm][kh][m * 16 + gp]     = dr0;
                    red[rlm][kh][m * 16 + gp + 8] = dr1;
                }
            }
            __syncthreads();

            // ---- e stage: warps 0..7, one per (rlm, k) ----
            if (w < 8) {
                const int rlm = w >> 1, kk = w & 1;
                const float* rrow = red[rlm][kk];
                float s = rrow[lane] + rrow[lane + 32] +
                          rrow[lane + 64] + rrow[lane + 96];
                #pragma unroll
                for (int sh = 16; sh >= 1; sh >>= 1)
                    s += __shfl_xor_sync(0xffffffffu, s, sh);
                if (lane == 0) {
                    float bn = s * INV_B;
                    const int gi = (r0 + mini * 4 + rlm) * 2 + kk;
                    if (pass) bn += g_b1[gi];
                    else      g_b1[gi] = bn;
                    float e = expf(bn);
                    ebc[rlm * 2 + kk] = e;
                    zacc += e;
                }
            }
            __syncthreads();

            // ---- weighted accumulation from retained fragments ----
            #pragma unroll
            for (int rlm = 0; rlm < 4; rlm++) {
                const float e = ebc[rlm * 2 + kh];
                const ull e2 = pack2(e, e);
                #pragma unroll
                for (int nt = 0; nt < 4; nt++) {
                    const float* C = CF[rlm][nt];
                    S2[0][nt] = fma2(pack2(C[0], C[1]), e2, S2[0][nt]);
                    S2[1][nt] = fma2(pack2(C[2], C[3]), e2, S2[1][nt]);
                }
            }
        }
    }

    float* dst = g_part[blockIdx.x];
    #pragma unroll
    for (int nt = 0; nt < 4; nt++) {
        const int ko = kh * 32 + nt * 8 + 2 * tig;
        const int b0 = m * 16 + gp;
        float lo, hi;
        unpack2(S2[0][nt], lo, hi);
        *(float2*)&dst[b0 * 64 + ko] = make_float2(lo, hi);
        unpack2(S2[1][nt], lo, hi);
        *(float2*)&dst[(b0 + 8) * 64 + ko] = make_float2(lo, hi);
    }
    if (w < 8 && lane == 0) atomicAdd(&g_Zf[pass * 2 + (w & 1)], zacc);
}

// ---------------------------------------------------------------------------
// Squash: sum 144 partials, normalize, squash. Warp per (b,k), lane = o.
// mode 0 additionally zeroes the Z accumulators for this launch.
// ---------------------------------------------------------------------------
__global__ void squash_kernel(int mode, float* __restrict__ out) {
    const int t = blockIdx.x * blockDim.x + threadIdx.x;   // 8192
    const int k = (t >> 5) & 1;
    if (mode == 0 && t < 4) g_Zf[t] = 0.f;
    float s = 0.f;
    #pragma unroll 4
    for (int c = 0; c < NCTA; c++) s += g_part[c][t];
    if (mode == 0) s *= INV_R;
    else           s /= g_Zf[(mode - 1) * 2 + k];
    float sq = s * s;
    #pragma unroll
    for (int m = 16; m >= 1; m >>= 1) sq += __shfl_xor_sync(0xffffffffu, sq, m);
    const float sn = sq;
    const float f = sqrtf(sn) / (0.5f + sn);
    const float v = s * f;
    if (mode == 2) out[t] = v;
    else           g_v[mode][t] = v;
}

// ---------------------------------------------------------------------------
extern "C" void kernel_launch(void* const* d_in, const int* in_sizes, int n_in,
                              void* d_out, int out_size) {
    const float* x = (const float*)d_in[0];   // [128, 4608, 16]
    const float* W = (const float*)d_in[1];   // [1, 4608, 2, 32, 16]
    float* out = (float*)d_out;               // [128, 2, 32]

    cudaFuncSetAttribute(pass0_mma,
                         cudaFuncAttributeMaxDynamicSharedMemorySize, DSM_BYTES);
    cudaFuncSetAttribute(routing_mma,
                         cudaFuncAttributeMaxDynamicSharedMemorySize, DSM_BYTES);

    pass0_mma<<<NCTA, 512, DSM_BYTES>>>((const float4*)x, (const float4*)W);
    squash_kernel<<<32, 256>>>(0, nullptr);
    routing_mma<<<NCTA, 512, DSM_BYTES>>>(0);
    squash_kernel<<<32, 256>>>(1, nullptr);
    routing_mma<<<NCTA, 512, DSM_BYTES>>>(1);
    squash_kernel<<<32, 256>>>(2, out);
}

// round 7
// speedup vs baseline: 6.1474x; 1.4373x over previous
#include <cuda_runtime.h>
#include <cuda_fp16.h>
#include <math.h>
#include <stdint.h>

#define BB 128
#define RR 4608
#define NR 8                 // r per staged batch
#define NBATCH 4
#define NRB (NR*NBATCH)      // 32 r per CTA
#define NCTA (RR/NRB)        // 144 -> one wave
#define INV_B (1.0f/128.0f)
#define INV_R (1.0f/4608.0f)

// smem tile geometry (48-byte padded rows -> conflict-free fragment LDS)
#define XROW 48
#define XT_RL (128*XROW)     // 6144 B per rl
#define WT_RL (64*XROW)      // 3072 B per rl
#define DSM_BYTES (NR*XT_RL + NR*WT_RL)   // 73728

typedef unsigned long long ull;

// fp16 copies of inputs (written by pass0 while it computes)
__device__ __half g_xh[(size_t)RR * BB * 16];    // [r][b][i]
__device__ __half g_wh[(size_t)RR * 64 * 16];    // [r][ko][i]
__device__ float g_part[NCTA][BB * 64];
__device__ float g_Zf[4];
__device__ float g_v[2][BB * 64];
__device__ float g_b1[RR * 2];

// ---------------- f32x2 helpers ------------------------------------------
__device__ __forceinline__ ull pack2(float lo, float hi) {
    ull r; asm("mov.b64 %0, {%1, %2};" : "=l"(r) : "f"(lo), "f"(hi)); return r;
}
__device__ __forceinline__ void unpack2(ull v, float& lo, float& hi) {
    asm("mov.b64 {%0, %1}, %2;" : "=f"(lo), "=f"(hi) : "l"(v));
}
__device__ __forceinline__ ull fma2(ull a, ull b, ull c) {
    ull d; asm("fma.rn.f32x2 %0, %1, %2, %3;" : "=l"(d) : "l"(a), "l"(b), "l"(c));
    return d;
}

// ---------------- m16n8k16 f16 MMA ---------------------------------------
__device__ __forceinline__ void mma16816(float* d, const uint32_t* a,
                                         const uint32_t* b, const float* c) {
    asm volatile(
        "mma.sync.aligned.m16n8k16.row.col.f32.f16.f16.f32 "
        "{%0,%1,%2,%3}, {%4,%5,%6,%7}, {%8,%9}, {%10,%11,%12,%13};"
        : "=f"(d[0]), "=f"(d[1]), "=f"(d[2]), "=f"(d[3])
        : "r"(a[0]), "r"(a[1]), "r"(a[2]), "r"(a[3]),
          "r"(b[0]), "r"(b[1]),
          "f"(c[0]), "f"(c[1]), "f"(c[2]), "f"(c[3]));
}

__device__ __forceinline__ uint2 cvt4(float4 v) {
    __half2 lo = __float22half2_rn(make_float2(v.x, v.y));
    __half2 hi = __float22half2_rn(make_float2(v.z, v.w));
    uint2 o; o.x = *(uint32_t*)&lo; o.y = *(uint32_t*)&hi;
    return o;
}

// ---------------------------------------------------------------------------
// Staging. pass0 variant: read fp32 inputs, convert, store tile + fp16 globals.
// routing variant: read the fp16 globals.
// ---------------------------------------------------------------------------
__device__ __forceinline__ void stage_conv(char* xt, char* wt,
                                           const float4* __restrict__ x4,
                                           const float4* __restrict__ w4,
                                           int r0, int t) {
    #pragma unroll
    for (int j = 0; j < 8; j++) {
        int idx = j * 512 + t;                      // 4096 uint2
        int rl = idx >> 9, rem = idx & 511, b = rem >> 2, q = rem & 3;
        uint2 u = cvt4(x4[((size_t)b * RR + r0 + rl) * 4 + q]);
        *(uint2*)(xt + rl * XT_RL + b * XROW + q * 8) = u;
        ((uint2*)g_xh)[((size_t)(r0 + rl) * BB + b) * 4 + q] = u;
    }
    #pragma unroll
    for (int j = 0; j < 4; j++) {
        int idx = j * 512 + t;                      // 2048 uint2
        int rl = idx >> 8, rem = idx & 255, ko = rem >> 2, q = rem & 3;
        uint2 u = cvt4(w4[((size_t)(r0 + rl) * 64 + ko) * 4 + q]);
        *(uint2*)(wt + rl * WT_RL + ko * XROW + q * 8) = u;
        ((uint2*)g_wh)[((size_t)(r0 + rl) * 64 + ko) * 4 + q] = u;
    }
}

__device__ __forceinline__ void stage_tiles(char* xt, char* wt, int r0, int t) {
    #pragma unroll
    for (int j = 0; j < 8; j++) {
        int idx = j * 512 + t;
        int rl = idx >> 9, rem = idx & 511, b = rem >> 2, q = rem & 3;
        uint2 v = ((const uint2*)g_xh)[((size_t)(r0 + rl) * BB + b) * 4 + q];
        *(uint2*)(xt + rl * XT_RL + b * XROW + q * 8) = v;
    }
    #pragma unroll
    for (int j = 0; j < 4; j++) {
        int idx = j * 512 + t;
        int rl = idx >> 8, rem = idx & 255, ko = rem >> 2, q = rem & 3;
        uint2 v = ((const uint2*)g_wh)[((size_t)(r0 + rl) * 64 + ko) * 4 + q];
        *(uint2*)(wt + rl * WT_RL + ko * XROW + q * 8) = v;
    }
}

__device__ __forceinline__ void load_a(const char* xb, uint32_t* A) {
    A[0] = *(const uint32_t*)(xb);
    A[1] = *(const uint32_t*)(xb + 8 * XROW);
    A[2] = *(const uint32_t*)(xb + 16);
    A[3] = *(const uint32_t*)(xb + 8 * XROW + 16);
}

// ---------------------------------------------------------------------------
// Pass 0 (+input conversion): s0 partial = sum over 32 r of u_hat via C accum.
// ---------------------------------------------------------------------------
__global__ __launch_bounds__(512, 1) void pass0_mma(const float4* __restrict__ x4,
                                                    const float4* __restrict__ w4) {
    extern __shared__ char dsm[];
    char* xt = dsm;
    char* wt = dsm + NR * XT_RL;
    const int t = threadIdx.x, lane = t & 31, w = t >> 5;
    const int m = w & 7, kh = w >> 3;
    const int gp = lane >> 2, tig = lane & 3;
    const int xoff = (m * 16 + gp) * XROW + tig * 4;
    const int woff = (kh * 32 + gp) * XROW + tig * 4;

    float CF[4][4];
    #pragma unroll
    for (int nt = 0; nt < 4; nt++)
        #pragma unroll
        for (int c = 0; c < 4; c++) CF[nt][c] = 0.f;

    const int rc = blockIdx.x * NRB;
    for (int bt = 0; bt < NBATCH; bt++) {
        if (bt) __syncthreads();
        stage_conv(xt, wt, x4, w4, rc + bt * NR, t);
        __syncthreads();
        #pragma unroll
        for (int rl = 0; rl < NR; rl++) {
            uint32_t A[4];
            load_a(xt + rl * XT_RL + xoff, A);
            const char* wb = wt + rl * WT_RL + woff;
            #pragma unroll
            for (int nt = 0; nt < 4; nt++) {
                uint32_t Bf[2];
                Bf[0] = *(const uint32_t*)(wb + nt * 8 * XROW);
                Bf[1] = *(const uint32_t*)(wb + nt * 8 * XROW + 16);
                mma16816(CF[nt], A, Bf, CF[nt]);
            }
        }
    }
    float* dst = g_part[blockIdx.x];
    #pragma unroll
    for (int nt = 0; nt < 4; nt++) {
        const int ko = kh * 32 + nt * 8 + 2 * tig;
        const int b0 = m * 16 + gp;
        *(float2*)&dst[b0 * 64 + ko]       = make_float2(CF[nt][0], CF[nt][1]);
        *(float2*)&dst[(b0 + 8) * 64 + ko] = make_float2(CF[nt][2], CF[nt][3]);
    }
}

// ---------------------------------------------------------------------------
// Routing pass (deferred softmax), single sweep with retained C fragments.
// Mini-batch of 4 rl: MMA+dots -> bar -> e-stage -> bar -> S += e*C (regs).
// ---------------------------------------------------------------------------
__global__ __launch_bounds__(512, 1) void routing_mma(int pass) {
    extern __shared__ char dsm[];
    char* xt = dsm;
    char* wt = dsm + NR * XT_RL;
    __shared__ float red[4][2][128];
    __shared__ float ebc[8];
    const int t = threadIdx.x, lane = t & 31, w = t >> 5;
    const int m = w & 7, kh = w >> 3;
    const int gp = lane >> 2, tig = lane & 3;
    const int xoff = (m * 16 + gp) * XROW + tig * 4;
    const int woff = (kh * 32 + gp) * XROW + tig * 4;

    // v fragments: v2[row][nt] covers (b=m*16+gp+row*8, ko=kh*32+nt*8+2*tig{,+1})
    ull v2[2][4];
    {
        const float* vp = g_v[pass];
        #pragma unroll
        for (int row = 0; row < 2; row++) {
            const int b = m * 16 + gp + row * 8;
            #pragma unroll
            for (int nt = 0; nt < 4; nt++) {
                float2 q = *(const float2*)&vp[b * 64 + kh * 32 + nt * 8 + 2 * tig];
                v2[row][nt] = pack2(q.x, q.y);
            }
        }
    }
    ull S2[2][4];
    #pragma unroll
    for (int row = 0; row < 2; row++)
        #pragma unroll
        for (int nt = 0; nt < 4; nt++) S2[row][nt] = 0ull;
    float zacc = 0.f;

    const int rc = blockIdx.x * NRB;
    for (int bt = 0; bt < NBATCH; bt++) {
        const int r0 = rc + bt * NR;
        stage_tiles(xt, wt, r0, t);
        __syncthreads();

        #pragma unroll
        for (int mini = 0; mini < 2; mini++) {
            float CF[4][4][4];   // [rlm][nt][c] retained across the e barrier

            // ---- sweep: u fragments + agreement dots ----
            #pragma unroll
            for (int rlm = 0; rlm < 4; rlm++) {
                const int rl = mini * 4 + rlm;
                uint32_t A[4];
                load_a(xt + rl * XT_RL + xoff, A);
                const char* wb = wt + rl * WT_RL + woff;
                ull d0 = 0ull, d1 = 0ull;
                #pragma unroll
                for (int nt = 0; nt < 4; nt++) {
                    uint32_t Bf[2];
                    Bf[0] = *(const uint32_t*)(wb + nt * 8 * XROW);
                    Bf[1] = *(const uint32_t*)(wb + nt * 8 * XROW + 16);
                    float* C = CF[rlm][nt];
                    C[0] = 0.f; C[1] = 0.f; C[2] = 0.f; C[3] = 0.f;
                    mma16816(C, A, Bf, C);
                    d0 = fma2(pack2(C[0], C[1]), v2[0][nt], d0);
                    d1 = fma2(pack2(C[2], C[3]), v2[1][nt], d1);
                }
                float l0, h0, l1, h1;
                unpack2(d0, l0, h0); unpack2(d1, l1, h1);
                float dr0 = l0 + h0, dr1 = l1 + h1;
                dr0 += __shfl_xor_sync(0xffffffffu, dr0, 1);
                dr0 += __shfl_xor_sync(0xffffffffu, dr0, 2);
                dr1 += __shfl_xor_sync(0xffffffffu, dr1, 1);
                dr1 += __shfl_xor_sync(0xffffffffu, dr1, 2);
                if (tig == 0) {
                    red[rlm][kh][m * 16 + gp]     = dr0;
                    red[rlm][kh][m * 16 + gp + 8] = dr1;
                }
            }
            __syncthreads();

            // ---- e stage: warps 0..7, one per (rlm, k) ----
            if (w < 8) {
                const int rlm = w >> 1, kk = w & 1;
                const float* rrow = red[rlm][kk];
                float s = rrow[lane] + rrow[lane + 32] +
                          rrow[lane + 64] + rrow[lane + 96];
                #pragma unroll
                for (int sh = 16; sh >= 1; sh >>= 1)
                    s += __shfl_xor_sync(0xffffffffu, s, sh);
                if (lane == 0) {
                    float bn = s * INV_B;
                    const int gi = (r0 + mini * 4 + rlm) * 2 + kk;
                    if (pass) bn += g_b1[gi];
                    else      g_b1[gi] = bn;
                    float e = expf(bn);
                    ebc[rlm * 2 + kk] = e;
                    zacc += e;
                }
            }
            __syncthreads();

            // ---- weighted accumulation from retained fragments ----
            #pragma unroll
            for (int rlm = 0; rlm < 4; rlm++) {
                const float e = ebc[rlm * 2 + kh];
                const ull e2 = pack2(e, e);
                #pragma unroll
                for (int nt = 0; nt < 4; nt++) {
                    const float* C = CF[rlm][nt];
                    S2[0][nt] = fma2(pack2(C[0], C[1]), e2, S2[0][nt]);
                    S2[1][nt] = fma2(pack2(C[2], C[3]), e2, S2[1][nt]);
                }
            }
        }
    }

    float* dst = g_part[blockIdx.x];
    #pragma unroll
    for (int nt = 0; nt < 4; nt++) {
        const int ko = kh * 32 + nt * 8 + 2 * tig;
        const int b0 = m * 16 + gp;
        float lo, hi;
        unpack2(S2[0][nt], lo, hi);
        *(float2*)&dst[b0 * 64 + ko] = make_float2(lo, hi);
        unpack2(S2[1][nt], lo, hi);
        *(float2*)&dst[(b0 + 8) * 64 + ko] = make_float2(lo, hi);
    }
    if (w < 8 && lane == 0) atomicAdd(&g_Zf[pass * 2 + (w & 1)], zacc);
}

// ---------------------------------------------------------------------------
// Squash, parallel reduction: one block per (b,k) capsule (256 blocks x 256
// threads). Thread (g,o): sum 18 of the 144 partials (coalesced over o),
// smem-reduce over g, warp 0 does the o-norm shuffle + squash + store.
// mode 0 also zeroes the Z accumulators for this launch (block 0).
// ---------------------------------------------------------------------------
__global__ __launch_bounds__(256) void squash_kernel(int mode, float* __restrict__ out) {
    __shared__ float sred[8][33];
    const int t = threadIdx.x;
    const int o = t & 31, g = t >> 5;
    const int cap = blockIdx.x;            // 0..255
    const int b = cap >> 1, k = cap & 1;
    if (mode == 0 && cap == 0 && t < 4) g_Zf[t] = 0.f;
    const int base = b * 64 + k * 32 + o;

    float s = 0.f;
    #pragma unroll
    for (int j = 0; j < NCTA / 8; j++)      // 18
        s += g_part[j * 8 + g][base];
    sred[g][o] = s;
    __syncthreads();

    if (g == 0) {
        float sum = sred[0][o] + sred[1][o] + sred[2][o] + sred[3][o] +
                    sred[4][o] + sred[5][o] + sred[6][o] + sred[7][o];
        if (mode == 0) sum *= INV_R;
        else           sum /= g_Zf[(mode - 1) * 2 + k];
        float sq = sum * sum;
        #pragma unroll
        for (int m = 16; m >= 1; m >>= 1) sq += __shfl_xor_sync(0xffffffffu, sq, m);
        const float sn = sq;
        const float f = sqrtf(sn) / (0.5f + sn);
        const float v = sum * f;
        if (mode == 2) out[base] = v;
        else           g_v[mode][base] = v;
    }
}

// ---------------------------------------------------------------------------
extern "C" void kernel_launch(void* const* d_in, const int* in_sizes, int n_in,
                              void* d_out, int out_size) {
    const float* x = (const float*)d_in[0];   // [128, 4608, 16]
    const float* W = (const float*)d_in[1];   // [1, 4608, 2, 32, 16]
    float* out = (float*)d_out;               // [128, 2, 32]

    cudaFuncSetAttribute(pass0_mma,
                         cudaFuncAttributeMaxDynamicSharedMemorySize, DSM_BYTES);
    cudaFuncSetAttribute(routing_mma,
                         cudaFuncAttributeMaxDynamicSharedMemorySize, DSM_BYTES);

    pass0_mma<<<NCTA, 512, DSM_BYTES>>>((const float4*)x, (const float4*)W);
    squash_kernel<<<256, 256>>>(0, nullptr);
    routing_mma<<<NCTA, 512, DSM_BYTES>>>(0);
    squash_kernel<<<256, 256>>>(1, nullptr);
    routing_mma<<<NCTA, 512, DSM_BYTES>>>(1);
    squash_kernel<<<256, 256>>>(2, out);
}